// round 4
// baseline (speedup 1.0000x reference)
#include <cuda_runtime.h>
#include <math.h>

#define N_NODES 1024
#define F_IN    256
#define HD      256
#define DD      64
#define MH      128
#define E_EDGES 32768

// Resolved input pointer table. Slots:
// 0=x 1=edge_index 2=edge_weight 3=W1 4=b1 5=W2 6=b2 7=dW1 8=db1 9=dW2 10=db2
__device__ const float* g_in[11];

// ---------------- device scratch (referenced ONLY inside device code) --------
__device__ float g_S[N_NODES * N_NODES];
__device__ float g_deg[N_NODES];
__device__ float g_dinv[N_NODES];
__device__ float g_lin1[N_NODES * HD];
__device__ float g_agg1[N_NODES * HD];
__device__ float g_h[N_NODES * HD];
__device__ float g_lin2[N_NODES * DD];
__device__ float g_agg2[N_NODES * DD];
__device__ float g_A[N_NODES * MH];
__device__ float g_B[N_NODES * MH];

// ---------------- input resolver (permutation-proof, kept for safety) -------
__global__ void k_resolve(const float* x, const float* ew, const float* b1,
                          const float* b2, const float* db2,
                          const void* p65a, const void* p65b,
                          const float* p16a, const float* p16b,
                          const float* p128a, const float* p128b) {
    __shared__ float red16[256];
    __shared__ float red128[256];
    __shared__ int isIdx;
    int t = threadIdx.x;               // 256
    if (t == 0) isIdx = 1;
    __syncthreads();
    unsigned uv = ((const unsigned*)p65a)[t * 256];
    if (uv >= 1024u) isIdx = 0;
    float s = 0.f;
    #pragma unroll
    for (int i = 0; i < 8; i++) { float v = p16a[t * 8 + i]; s += v * v; }
    red16[t] = s;
    float v2 = (t < 128) ? p128a[t] : 0.f;
    red128[t] = v2 * v2;
    __syncthreads();
    for (int off = 128; off > 0; off >>= 1) {
        if (t < off) { red16[t] += red16[t + off]; red128[t] += red128[t + off]; }
        __syncthreads();
    }
    if (t == 0) {
        g_in[0] = x; g_in[2] = ew; g_in[4] = b1; g_in[6] = b2; g_in[10] = db2;
        bool aIdx = (isIdx != 0);
        g_in[1] = (const float*)(aIdx ? p65a : p65b);
        g_in[3] = (const float*)(aIdx ? p65b : p65a);
        bool aW2 = (red16[0] < 12.0f);          // W2 sumsq~8, dW1 sumsq~16
        g_in[5] = aW2 ? p16a : p16b;
        g_in[7] = aW2 ? p16b : p16a;
        bool aDb1 = (red128[0] < 0.01f);        // db1 all-zero
        g_in[8] = aDb1 ? p128a : p128b;
        g_in[9] = aDb1 ? p128b : p128a;
    }
}

// ---------------- S build ----------------
__global__ void k_zeroS() {
    int i = blockIdx.x * blockDim.x + threadIdx.x;
    g_S[i] = 0.0f;
}
__global__ void k_zeroDeg() {
    int i = blockIdx.x * blockDim.x + threadIdx.x;
    g_deg[i] = 0.0f;
}
__global__ void k_degree() {
    int e = blockIdx.x * blockDim.x + threadIdx.x;
    if (e >= E_EDGES) return;
    const int* ei = (const int*)g_in[1];
    int c = ei[E_EDGES + e] & (N_NODES - 1);
    atomicAdd(&g_deg[c], g_in[2][e]);
}
__global__ void k_dinv() {
    int i = blockIdx.x * blockDim.x + threadIdx.x;
    g_dinv[i] = rsqrtf(g_deg[i] + 1.0f);        // +1 self-loop weight
}
__global__ void k_scatter() {
    int e = blockIdx.x * blockDim.x + threadIdx.x;
    if (e >= E_EDGES) return;
    const int* ei = (const int*)g_in[1];
    int r = ei[e] & (N_NODES - 1);
    int c = ei[E_EDGES + e] & (N_NODES - 1);
    float v = g_dinv[r] * g_in[2][e] * g_dinv[c];
    atomicAdd(&g_S[c * N_NODES + r], v);
}
__global__ void k_diag() {
    int i = blockIdx.x * blockDim.x + threadIdx.x;
    float d = g_dinv[i];
    atomicAdd(&g_S[i * N_NODES + i], d * d);
}

// ---------------- 64x64-tile GEMM, operands bound in DEVICE code -------------
// OP0: lin1 = x @ W1          (M=1024,N=256,K=256)
// OP1: agg1 = S @ lin1        (M=1024,N=256,K=1024)
// OP4: g_A = z @ dW1[:DD]     (M=1024,N=128,K=64)   z = extA (d_out)
// OP5: g_B = z @ dW1[DD:]     (M=1024,N=128,K=64)
template<int OP>
__global__ __launch_bounds__(256) void gemm64(const float* extA) {
    constexpr int N = (OP == 0) ? HD : (OP == 1) ? HD : MH;
    constexpr int K = (OP == 0) ? F_IN : (OP == 1) ? N_NODES : DD;
    const float* __restrict__ A;
    const float* __restrict__ B;
    float* __restrict__ C;
    if      (OP == 0) { A = g_in[0]; B = g_in[3];           C = g_lin1; }
    else if (OP == 1) { A = g_S;     B = g_lin1;            C = g_agg1; }
    else if (OP == 4) { A = extA;    B = g_in[7];           C = g_A;    }
    else              { A = extA;    B = g_in[7] + DD * MH; C = g_B;    }

    __shared__ float As[16][65];   // [k][m]
    __shared__ float Bs[16][65];   // [k][n]
    int tid = threadIdx.x;
    int tx = tid & 15, ty = tid >> 4;
    int m0 = blockIdx.y * 64, n0 = blockIdx.x * 64;
    float acc[4][4] = {};
    for (int k0 = 0; k0 < K; k0 += 16) {
        #pragma unroll
        for (int v = 0; v < 4; v++) {
            int q  = tid + 256 * v;
            int ka = q & 15, ma = q >> 4;
            As[ka][ma] = A[(m0 + ma) * K + k0 + ka];
            int nb = q & 63, kb = q >> 6;
            Bs[kb][nb] = B[(k0 + kb) * N + n0 + nb];
        }
        __syncthreads();
        #pragma unroll
        for (int k = 0; k < 16; k++) {
            float a[4], b[4];
            #pragma unroll
            for (int ii = 0; ii < 4; ii++) a[ii] = As[k][ty + 16 * ii];
            #pragma unroll
            for (int jj = 0; jj < 4; jj++) b[jj] = Bs[k][tx + 16 * jj];
            #pragma unroll
            for (int ii = 0; ii < 4; ii++)
                #pragma unroll
                for (int jj = 0; jj < 4; jj++)
                    acc[ii][jj] = fmaf(a[ii], b[jj], acc[ii][jj]);
        }
        __syncthreads();
    }
    #pragma unroll
    for (int ii = 0; ii < 4; ii++)
        #pragma unroll
        for (int jj = 0; jj < 4; jj++)
            C[(m0 + ty + 16 * ii) * N + n0 + tx + 16 * jj] = acc[ii][jj];
}

// ---------------- 16x64-tile GEMM for N=64 ops (64 blocks each) --------------
// OP2: lin2 = h @ W2     (K=256)     OP3: agg2 = S @ lin2  (K=1024)
template<int OP>
__global__ __launch_bounds__(256) void gemmN64() {
    constexpr int K = (OP == 2) ? HD : N_NODES;
    const float* __restrict__ A = (OP == 2) ? g_h : g_S;
    const float* __restrict__ B;
    if (OP == 2) B = g_in[5]; else B = g_lin2;
    float* __restrict__ C = (OP == 2) ? g_lin2 : g_agg2;

    __shared__ float As[16][17];
    __shared__ float Bs[16][64];
    int tid = threadIdx.x;
    int c = tid & 63, r4 = tid >> 6;            // 4 row-groups
    int m0 = blockIdx.x * 16;
    float acc[4] = {};
    for (int k0 = 0; k0 < K; k0 += 16) {
        { int r = tid >> 4, kk = tid & 15;
          As[r][kk] = A[(m0 + r) * K + k0 + kk]; }
        #pragma unroll
        for (int v = 0; v < 4; v++) {
            int q = tid + 256 * v;
            int kk = q >> 6, cc = q & 63;
            Bs[kk][cc] = B[(k0 + kk) * DD + cc];
        }
        __syncthreads();
        #pragma unroll
        for (int kk = 0; kk < 16; kk++) {
            float b = Bs[kk][c];
            #pragma unroll
            for (int rr = 0; rr < 4; rr++)
                acc[rr] = fmaf(As[r4 + 4 * rr][kk], b, acc[rr]);
        }
        __syncthreads();
    }
    #pragma unroll
    for (int rr = 0; rr < 4; rr++)
        C[(m0 + r4 + 4 * rr) * DD + c] = acc[rr];
}

// ---------------- elementwise ----------------
__global__ void k_hrelu() {
    int n = blockIdx.x;
    int f = threadIdx.x;                        // 256
    float v = g_agg1[n * HD + f] + g_in[4][f];
    g_h[n * HD + f] = fmaxf(v, 0.0f);
}
__global__ void k_addb2(float* __restrict__ outz) {
    int n = blockIdx.x;
    int f = threadIdx.x;                        // 64
    outz[n * DD + f] = g_agg2[n * DD + f] + g_in[6][f];
}

// ---------------- decoder ----------------
__global__ __launch_bounds__(256) void k_dec(float* __restrict__ adj) {
    const float* __restrict__ db1 = g_in[8];
    const float* __restrict__ dW2 = g_in[9];
    __shared__ float sA[64][65];    // [i_local][h]
    __shared__ float sB[64][65];    // [j_local][h]
    __shared__ float sW[MH];
    int tid = threadIdx.x;
    int tx = tid & 15, ty = tid >> 4;
    int i0 = blockIdx.y * 64, j0 = blockIdx.x * 64;
    if (tid < MH) sW[tid] = dW2[tid];
    float acc[4][4] = {};
    for (int hc = 0; hc < 2; hc++) {
        __syncthreads();
        #pragma unroll
        for (int v = 0; v < 4; v++) {
            int q   = tid + 256 * v;
            int row = q >> 4;
            int h4  = q & 15;
            float4 a4 = *(const float4*)(g_A + (i0 + row) * MH + hc * 64 + h4 * 4);
            float4 d4 = *(const float4*)(db1 + hc * 64 + h4 * 4);
            sA[row][h4 * 4 + 0] = a4.x + d4.x;
            sA[row][h4 * 4 + 1] = a4.y + d4.y;
            sA[row][h4 * 4 + 2] = a4.z + d4.z;
            sA[row][h4 * 4 + 3] = a4.w + d4.w;
            float4 b4 = *(const float4*)(g_B + (j0 + row) * MH + hc * 64 + h4 * 4);
            sB[row][h4 * 4 + 0] = b4.x;
            sB[row][h4 * 4 + 1] = b4.y;
            sB[row][h4 * 4 + 2] = b4.z;
            sB[row][h4 * 4 + 3] = b4.w;
        }
        __syncthreads();
        #pragma unroll
        for (int h = 0; h < 64; h++) {
            float w = sW[hc * 64 + h];
            float a[4], b[4];
            #pragma unroll
            for (int ii = 0; ii < 4; ii++) a[ii] = sA[ty + 16 * ii][h];
            #pragma unroll
            for (int jj = 0; jj < 4; jj++) b[jj] = sB[tx + 16 * jj][h];
            #pragma unroll
            for (int ii = 0; ii < 4; ii++)
                #pragma unroll
                for (int jj = 0; jj < 4; jj++) {
                    float t = fmaxf(a[ii] + b[jj], 0.0f);
                    acc[ii][jj] = fmaf(t, w, acc[ii][jj]);
                }
        }
    }
    float bb = g_in[10][0];
    #pragma unroll
    for (int ii = 0; ii < 4; ii++) {
        int i = i0 + ty + 16 * ii;
        #pragma unroll
        for (int jj = 0; jj < 4; jj++) {
            int j = j0 + tx + 16 * jj;
            float v = acc[ii][jj] + bb;
            adj[i * N_NODES + j] = 1.0f / (1.0f + __expf(-v));
        }
    }
}

// ---------------- launch (only harness pointers cross the boundary) ----------
extern "C" void kernel_launch(void* const* d_in, const int* in_sizes, int n_in,
                              void* d_out, int out_size) {
    const float *x = 0, *ew = 0, *b1 = 0, *b2 = 0, *db2 = 0;
    const void *p65a = 0, *p65b = 0;
    const float *p16a = 0, *p16b = 0, *p128a = 0, *p128b = 0;
    for (int i = 0; i < n_in; i++) {
        int s = in_sizes[i];
        const void* p = d_in[i];
        if      (s == 262144) x   = (const float*)p;
        else if (s == 32768)  ew  = (const float*)p;
        else if (s == 256)    b1  = (const float*)p;
        else if (s == 64)     b2  = (const float*)p;
        else if (s == 1)      db2 = (const float*)p;
        else if (s == 65536)  { if (!p65a)  p65a  = p; else p65b  = p; }
        else if (s == 16384)  { if (!p16a)  p16a  = (const float*)p; else p16b  = (const float*)p; }
        else if (s == 128)    { if (!p128a) p128a = (const float*)p; else p128b = (const float*)p; }
    }

    float* outz = (float*)d_out;                 // [1024, 64]
    float* adj  = outz + N_NODES * DD;           // [1024, 1024]

    k_resolve<<<1, 256>>>(x, ew, b1, b2, db2, p65a, p65b, p16a, p16b, p128a, p128b);

    k_zeroS  <<<N_NODES * N_NODES / 256, 256>>>();
    k_zeroDeg<<<N_NODES / 256, 256>>>();
    k_degree <<<E_EDGES / 256, 256>>>();
    k_dinv   <<<N_NODES / 256, 256>>>();
    k_scatter<<<E_EDGES / 256, 256>>>();
    k_diag   <<<N_NODES / 256, 256>>>();

    // Layer 1
    gemm64<0><<<dim3(HD / 64, N_NODES / 64), 256>>>(nullptr);
    gemm64<1><<<dim3(HD / 64, N_NODES / 64), 256>>>(nullptr);
    k_hrelu<<<N_NODES, HD>>>();

    // Layer 2
    gemmN64<2><<<N_NODES / 16, 256>>>();
    gemmN64<3><<<N_NODES / 16, 256>>>();
    k_addb2<<<N_NODES, DD>>>(outz);

    // Decoder operands
    gemm64<4><<<dim3(MH / 64, N_NODES / 64), 256>>>(outz);
    gemm64<5><<<dim3(MH / 64, N_NODES / 64), 256>>>(outz);

    // Decoder
    k_dec<<<dim3(N_NODES / 64, N_NODES / 64), 256>>>(adj);
}

// round 5
// speedup vs baseline: 2.1747x; 2.1747x over previous
#include <cuda_runtime.h>
#include <math.h>

#define N_NODES 1024
#define F_IN    256
#define HD      256
#define DD      64
#define MH      128
#define E_EDGES 32768

// Resolved input pointer table. Slots:
// 0=x 1=edge_index 2=edge_weight 3=W1 4=b1 5=W2 6=b2 7=dW1 8=db1 9=dW2 10=db2
__device__ const float* g_in[11];

// ---------------- device scratch (referenced ONLY inside device code) --------
__device__ float g_deg[N_NODES];
__device__ float g_dinv[N_NODES];
__device__ int   g_cnt[N_NODES];
__device__ int   g_start[N_NODES];
__device__ int   g_fill[N_NODES];
__device__ int   g_csr_row[E_EDGES];
__device__ float g_csr_coef[E_EDGES];
__device__ float g_lin1[N_NODES * HD];
__device__ float g_h[N_NODES * HD];
__device__ float g_lin2[N_NODES * DD];
__device__ float g_A[N_NODES * MH];
__device__ float g_B[N_NODES * MH];

// ---------------- input resolver (permutation-proof) ----------------
__global__ void k_resolve(const float* x, const float* ew, const float* b1,
                          const float* b2, const float* db2,
                          const void* p65a, const void* p65b,
                          const float* p16a, const float* p16b,
                          const float* p128a, const float* p128b) {
    __shared__ float red16[256];
    __shared__ float red128[256];
    __shared__ int isIdx;
    int t = threadIdx.x;               // 256
    if (t == 0) isIdx = 1;
    __syncthreads();
    unsigned uv = ((const unsigned*)p65a)[t * 256];
    if (uv >= 1024u) isIdx = 0;
    float s = 0.f;
    #pragma unroll
    for (int i = 0; i < 8; i++) { float v = p16a[t * 8 + i]; s += v * v; }
    red16[t] = s;
    float v2 = (t < 128) ? p128a[t] : 0.f;
    red128[t] = v2 * v2;
    __syncthreads();
    for (int off = 128; off > 0; off >>= 1) {
        if (t < off) { red16[t] += red16[t + off]; red128[t] += red128[t + off]; }
        __syncthreads();
    }
    if (t == 0) {
        g_in[0] = x; g_in[2] = ew; g_in[4] = b1; g_in[6] = b2; g_in[10] = db2;
        bool aIdx = (isIdx != 0);
        g_in[1] = (const float*)(aIdx ? p65a : p65b);
        g_in[3] = (const float*)(aIdx ? p65b : p65a);
        bool aW2 = (red16[0] < 12.0f);          // W2 sumsq~8, dW1 sumsq~16
        g_in[5] = aW2 ? p16a : p16b;
        g_in[7] = aW2 ? p16b : p16a;
        bool aDb1 = (red128[0] < 0.01f);        // db1 all-zero
        g_in[8] = aDb1 ? p128a : p128b;
        g_in[9] = aDb1 ? p128b : p128a;
    }
}

// ---------------- CSR build ----------------
__global__ void k_prep() {
    int i = blockIdx.x * blockDim.x + threadIdx.x;   // 4x256
    g_deg[i] = 0.f; g_cnt[i] = 0; g_fill[i] = 0;
}
__global__ void k_count() {
    int e = blockIdx.x * blockDim.x + threadIdx.x;
    if (e >= E_EDGES) return;
    const int* ei = (const int*)g_in[1];
    int c = ei[E_EDGES + e] & (N_NODES - 1);
    atomicAdd(&g_deg[c], g_in[2][e]);
    atomicAdd(&g_cnt[c], 1);
}
__global__ void k_scan() {              // 1 block, 1024 threads
    __shared__ int sc[N_NODES];
    int t = threadIdx.x;
    int v = g_cnt[t];
    sc[t] = v;
    __syncthreads();
    for (int off = 1; off < N_NODES; off <<= 1) {
        int add = (t >= off) ? sc[t - off] : 0;
        __syncthreads();
        sc[t] += add;
        __syncthreads();
    }
    g_start[t] = sc[t] - v;
    g_dinv[t]  = rsqrtf(g_deg[t] + 1.0f);   // +1 self-loop weight
}
__global__ void k_fill() {
    int e = blockIdx.x * blockDim.x + threadIdx.x;
    if (e >= E_EDGES) return;
    const int* ei = (const int*)g_in[1];
    int r = ei[e] & (N_NODES - 1);
    int c = ei[E_EDGES + e] & (N_NODES - 1);
    int p = g_start[c] + atomicAdd(&g_fill[c], 1);
    g_csr_row[p]  = r;
    g_csr_coef[p] = g_dinv[r] * g_in[2][e] * g_dinv[c];
}

// ---------------- 64x64-tile GEMM: lin1 = x @ W1 ----------------
__global__ __launch_bounds__(256) void gemm_lin1() {
    const float* __restrict__ A = g_in[0];
    const float* __restrict__ B = g_in[3];
    float* __restrict__ C = g_lin1;
    __shared__ float As[16][65];
    __shared__ float Bs[16][65];
    int tid = threadIdx.x;
    int tx = tid & 15, ty = tid >> 4;
    int m0 = blockIdx.y * 64, n0 = blockIdx.x * 64;
    float acc[4][4] = {};
    for (int k0 = 0; k0 < F_IN; k0 += 16) {
        #pragma unroll
        for (int v = 0; v < 4; v++) {
            int q  = tid + 256 * v;
            int ka = q & 15, ma = q >> 4;
            As[ka][ma] = A[(m0 + ma) * F_IN + k0 + ka];
            int nb = q & 63, kb = q >> 6;
            Bs[kb][nb] = B[(k0 + kb) * HD + n0 + nb];
        }
        __syncthreads();
        #pragma unroll
        for (int k = 0; k < 16; k++) {
            float a[4], b[4];
            #pragma unroll
            for (int ii = 0; ii < 4; ii++) a[ii] = As[k][ty + 16 * ii];
            #pragma unroll
            for (int jj = 0; jj < 4; jj++) b[jj] = Bs[k][tx + 16 * jj];
            #pragma unroll
            for (int ii = 0; ii < 4; ii++)
                #pragma unroll
                for (int jj = 0; jj < 4; jj++)
                    acc[ii][jj] = fmaf(a[ii], b[jj], acc[ii][jj]);
        }
        __syncthreads();
    }
    #pragma unroll
    for (int ii = 0; ii < 4; ii++)
        #pragma unroll
        for (int jj = 0; jj < 4; jj++)
            C[(m0 + ty + 16 * ii) * HD + n0 + tx + 16 * jj] = acc[ii][jj];
}

// ---------------- agg1 = S @ lin1 (+b1, relu) via CSR gather -----------------
__global__ __launch_bounds__(256) void k_agg1() {
    __shared__ int   sr[256];
    __shared__ float scf[256];
    int c = blockIdx.x;
    int f = threadIdx.x;                    // 256
    float di = g_dinv[c];
    float s = di * di * g_lin1[c * HD + f]; // self-loop
    int st = g_start[c], cn = g_cnt[c];
    for (int base = 0; base < cn; base += 256) {
        int m = cn - base; if (m > 256) m = 256;
        if (f < m) { sr[f] = g_csr_row[st + base + f]; scf[f] = g_csr_coef[st + base + f]; }
        __syncthreads();
        #pragma unroll 4
        for (int i = 0; i < m; i++)
            s = fmaf(scf[i], g_lin1[sr[i] * HD + f], s);
        __syncthreads();
    }
    s += g_in[4][f];
    g_h[c * HD + f] = fmaxf(s, 0.0f);
}

// ---------------- lin2 = h @ W2 (16x64 tiles, 64 blocks) ----------------
__global__ __launch_bounds__(256) void gemm_lin2() {
    const float* __restrict__ A = g_h;
    float* __restrict__ C = g_lin2;
    __shared__ float As[16][17];
    __shared__ float Bs[16][64];
    int tid = threadIdx.x;
    int c = tid & 63, r4 = tid >> 6;
    int m0 = blockIdx.x * 16;
    float acc[4] = {};
    const float* __restrict__ B = g_in[5];
    for (int k0 = 0; k0 < HD; k0 += 16) {
        { int r = tid >> 4, kk = tid & 15;
          As[r][kk] = A[(m0 + r) * HD + k0 + kk]; }
        { int kk = tid >> 6, cc = tid & 63;
          Bs[kk][cc] = B[(k0 + kk) * DD + cc];
          Bs[kk + 4][cc] = B[(k0 + kk + 4) * DD + cc];
          Bs[kk + 8][cc] = B[(k0 + kk + 8) * DD + cc];
          Bs[kk + 12][cc] = B[(k0 + kk + 12) * DD + cc]; }
        __syncthreads();
        #pragma unroll
        for (int kk = 0; kk < 16; kk++) {
            float b = Bs[kk][c];
            #pragma unroll
            for (int rr = 0; rr < 4; rr++)
                acc[rr] = fmaf(As[r4 + 4 * rr][kk], b, acc[rr]);
        }
        __syncthreads();
    }
    #pragma unroll
    for (int rr = 0; rr < 4; rr++)
        C[(m0 + r4 + 4 * rr) * DD + c] = acc[rr];
}

// ---------------- z = S @ lin2 + b2 -> d_out via CSR gather ------------------
__global__ __launch_bounds__(64) void k_agg2(float* __restrict__ outz) {
    int c = blockIdx.x;
    int f = threadIdx.x;                    // 64
    float di = g_dinv[c];
    float s = di * di * g_lin2[c * DD + f];
    int st = g_start[c], cn = g_cnt[c];
    #pragma unroll 4
    for (int i = 0; i < cn; i++) {
        int   r  = g_csr_row[st + i];
        float cf = g_csr_coef[st + i];
        s = fmaf(cf, g_lin2[r * DD + f], s);
    }
    outz[c * DD + f] = s + g_in[6][f];
}

// ---------------- A/B operands: [A|B] = z @ dW1 halves (one launch) ----------
__global__ __launch_bounds__(256) void gemm_ab(const float* __restrict__ Z) {
    const float* __restrict__ B = g_in[7] + (blockIdx.z ? DD * MH : 0);
    float* __restrict__ C = blockIdx.z ? g_B : g_A;
    __shared__ float As[16][65];
    __shared__ float Bs[16][65];
    int tid = threadIdx.x;
    int tx = tid & 15, ty = tid >> 4;
    int m0 = blockIdx.y * 64, n0 = blockIdx.x * 64;
    float acc[4][4] = {};
    for (int k0 = 0; k0 < DD; k0 += 16) {
        #pragma unroll
        for (int v = 0; v < 4; v++) {
            int q  = tid + 256 * v;
            int ka = q & 15, ma = q >> 4;
            As[ka][ma] = Z[(m0 + ma) * DD + k0 + ka];
            int nb = q & 63, kb = q >> 6;
            Bs[kb][nb] = B[(k0 + kb) * MH + n0 + nb];
        }
        __syncthreads();
        #pragma unroll
        for (int k = 0; k < 16; k++) {
            float a[4], b[4];
            #pragma unroll
            for (int ii = 0; ii < 4; ii++) a[ii] = As[k][ty + 16 * ii];
            #pragma unroll
            for (int jj = 0; jj < 4; jj++) b[jj] = Bs[k][tx + 16 * jj];
            #pragma unroll
            for (int ii = 0; ii < 4; ii++)
                #pragma unroll
                for (int jj = 0; jj < 4; jj++)
                    acc[ii][jj] = fmaf(a[ii], b[jj], acc[ii][jj]);
        }
        __syncthreads();
    }
    #pragma unroll
    for (int ii = 0; ii < 4; ii++)
        #pragma unroll
        for (int jj = 0; jj < 4; jj++)
            C[(m0 + ty + 16 * ii) * MH + n0 + tx + 16 * jj] = acc[ii][jj];
}

// ---------------- decoder ----------------
__global__ __launch_bounds__(256) void k_dec(float* __restrict__ adj) {
    const float* __restrict__ db1 = g_in[8];
    const float* __restrict__ dW2 = g_in[9];
    __shared__ float sA[64][65];    // [i_local][h]
    __shared__ float sB[64][65];    // [j_local][h]
    __shared__ float sW[MH];
    int tid = threadIdx.x;
    int tx = tid & 15, ty = tid >> 4;
    int i0 = blockIdx.y * 64, j0 = blockIdx.x * 64;
    if (tid < MH) sW[tid] = dW2[tid];
    float acc[4][4] = {};
    for (int hc = 0; hc < 2; hc++) {
        __syncthreads();
        #pragma unroll
        for (int v = 0; v < 4; v++) {
            int q   = tid + 256 * v;
            int row = q >> 4;
            int h4  = q & 15;
            float4 a4 = *(const float4*)(g_A + (i0 + row) * MH + hc * 64 + h4 * 4);
            float4 d4 = *(const float4*)(db1 + hc * 64 + h4 * 4);
            sA[row][h4 * 4 + 0] = a4.x + d4.x;
            sA[row][h4 * 4 + 1] = a4.y + d4.y;
            sA[row][h4 * 4 + 2] = a4.z + d4.z;
            sA[row][h4 * 4 + 3] = a4.w + d4.w;
            float4 b4 = *(const float4*)(g_B + (j0 + row) * MH + hc * 64 + h4 * 4);
            sB[row][h4 * 4 + 0] = b4.x;
            sB[row][h4 * 4 + 1] = b4.y;
            sB[row][h4 * 4 + 2] = b4.z;
            sB[row][h4 * 4 + 3] = b4.w;
        }
        __syncthreads();
        #pragma unroll
        for (int h = 0; h < 64; h++) {
            float w = sW[hc * 64 + h];
            float a[4], b[4];
            #pragma unroll
            for (int ii = 0; ii < 4; ii++) a[ii] = sA[ty + 16 * ii][h];
            #pragma unroll
            for (int jj = 0; jj < 4; jj++) b[jj] = sB[tx + 16 * jj][h];
            #pragma unroll
            for (int ii = 0; ii < 4; ii++)
                #pragma unroll
                for (int jj = 0; jj < 4; jj++) {
                    float t = fmaxf(a[ii] + b[jj], 0.0f);
                    acc[ii][jj] = fmaf(t, w, acc[ii][jj]);
                }
        }
    }
    float bb = g_in[10][0];
    #pragma unroll
    for (int ii = 0; ii < 4; ii++) {
        int i = i0 + ty + 16 * ii;
        #pragma unroll
        for (int jj = 0; jj < 4; jj++) {
            int j = j0 + tx + 16 * jj;
            float v = acc[ii][jj] + bb;
            adj[i * N_NODES + j] = 1.0f / (1.0f + __expf(-v));
        }
    }
}

// ---------------- launch ----------------
extern "C" void kernel_launch(void* const* d_in, const int* in_sizes, int n_in,
                              void* d_out, int out_size) {
    const float *x = 0, *ew = 0, *b1 = 0, *b2 = 0, *db2 = 0;
    const void *p65a = 0, *p65b = 0;
    const float *p16a = 0, *p16b = 0, *p128a = 0, *p128b = 0;
    for (int i = 0; i < n_in; i++) {
        int s = in_sizes[i];
        const void* p = d_in[i];
        if      (s == 262144) x   = (const float*)p;
        else if (s == 32768)  ew  = (const float*)p;
        else if (s == 256)    b1  = (const float*)p;
        else if (s == 64)     b2  = (const float*)p;
        else if (s == 1)      db2 = (const float*)p;
        else if (s == 65536)  { if (!p65a)  p65a  = p; else p65b  = p; }
        else if (s == 16384)  { if (!p16a)  p16a  = (const float*)p; else p16b  = (const float*)p; }
        else if (s == 128)    { if (!p128a) p128a = (const float*)p; else p128b = (const float*)p; }
    }

    float* outz = (float*)d_out;                 // [1024, 64]
    float* adj  = outz + N_NODES * DD;           // [1024, 1024]

    k_resolve<<<1, 256>>>(x, ew, b1, b2, db2, p65a, p65b, p16a, p16b, p128a, p128b);

    // CSR build
    k_prep <<<N_NODES / 256, 256>>>();
    k_count<<<E_EDGES / 256, 256>>>();
    k_scan <<<1, N_NODES>>>();
    k_fill <<<E_EDGES / 256, 256>>>();

    // Layer 1: lin1 = x@W1 ; h = relu(S@lin1 + b1)
    gemm_lin1<<<dim3(HD / 64, N_NODES / 64), 256>>>();
    k_agg1<<<N_NODES, 256>>>();

    // Layer 2: lin2 = h@W2 ; z = S@lin2 + b2 -> d_out
    gemm_lin2<<<N_NODES / 16, 256>>>();
    k_agg2<<<N_NODES, 64>>>(outz);

    // Decoder operands (A and B in one launch) + decoder
    gemm_ab<<<dim3(MH / 64, N_NODES / 64, 2), 256>>>(outz);
    k_dec<<<dim3(N_NODES / 64, N_NODES / 64), 256>>>(adj);
}